// round 9
// baseline (speedup 1.0000x reference)
#include <cuda_runtime.h>

// Involution: B=4 H=56 W=56 C=256, K=7 (pad 3), G=16, Cg=16, Cr=64, eps=1e-3
//
// K1: r[b][d][hw] = ReLU(BN(x @ w_reduce)) -> scratch, f32x2 math. (unchanged)
// K2 @ 3 CTA/SM (72.6KB smem): span GEMM (f32x2) -> kgen in smem; involution as
//     4 single-row passes, each staging a 7-row x halo (float2, stride-437 c2
//     layout) aliased over the dead r/w smem.

#define HH 56
#define WW 56
#define CCH 256
#define CR 64
#define GG 16
#define PIX_PER_B (HH * WW)          // 3136
#define NPIX (4 * PIX_PER_B)         // 12544

typedef unsigned long long ull;

__device__ __forceinline__ ull f2pack(float a, float b) {
    ull r; asm("mov.b64 %0, {%1, %2};" : "=l"(r) : "f"(a), "f"(b)); return r;
}
__device__ __forceinline__ ull f2splat(float a) {
    ull r; asm("mov.b64 %0, {%1, %1};" : "=l"(r) : "f"(a)); return r;
}
__device__ __forceinline__ void f2unpack(ull v, float& a, float& b) {
    asm("mov.b64 {%0, %1}, %2;" : "=f"(a), "=f"(b) : "l"(v));
}
__device__ __forceinline__ ull f2fma(ull a, ull b, ull c) {
    ull d; asm("fma.rn.f32x2 %0, %1, %2, %3;" : "=l"(d) : "l"(a), "l"(b), "l"(c)); return d;
}

// scratch: r activations, layout [b][d][hw]
__device__ __align__(16) float g_r[4 * CR * PIX_PER_B];

// ---------------------------------------------------------------------------
// K1: unchanged from R8 (measured ~16.5us, 6 CTA/SM)
// ---------------------------------------------------------------------------
__global__ void __launch_bounds__(128, 6)
k_reduce(const float* __restrict__ x,
         const float* __restrict__ w_reduce,
         const float* __restrict__ gamma,
         const float* __restrict__ beta,
         const float* __restrict__ mean,
         const float* __restrict__ var)
{
    extern __shared__ float sm1[];
    float* xs = sm1;                 // [64][66]
    float* ws = sm1 + 64 * 66;       // [64][68]

    const int t    = threadIdx.x;
    const int pix0 = blockIdx.x * 64;
    const int b    = pix0 / PIX_PER_B;
    const int hw0  = pix0 % PIX_PER_B;

    const int dq = t & 15;
    const int pq = t >> 4;

    ull acc2[8][2];
#pragma unroll
    for (int j = 0; j < 8; j++) { acc2[j][0] = 0ull; acc2[j][1] = 0ull; }

    const float2* xg2 = (const float2*)x;
    const float4* wg  = (const float4*)w_reduce;

    for (int c0 = 0; c0 < 256; c0 += 64) {
        if (c0) __syncthreads();
#pragma unroll
        for (int it = 0; it < 16; it++) {
            const int i2 = t + it * 128;
            const int p = i2 >> 5, c2 = i2 & 31;
            *(float2*)(xs + p * 66 + c2 * 2) =
                xg2[(size_t)(pix0 + p) * 128 + (c0 >> 1) + c2];
        }
#pragma unroll
        for (int it = 0; it < 8; it++) {
            const int i4 = t + it * 128;
            const int c = i4 >> 4, d4 = i4 & 15;
            *(float4*)(ws + c * 68 + d4 * 4) = wg[(size_t)(c0 + c) * 16 + d4];
        }
        __syncthreads();

#pragma unroll 4
        for (int c = 0; c < 64; c++) {
            const float4 w = *(const float4*)(ws + c * 68 + dq * 4);
            const ull wlo = f2pack(w.x, w.y);
            const ull whi = f2pack(w.z, w.w);
#pragma unroll
            for (int j = 0; j < 8; j++) {
                const ull xp = f2splat(xs[(pq * 8 + j) * 66 + c]);
                acc2[j][0] = f2fma(xp, wlo, acc2[j][0]);
                acc2[j][1] = f2fma(xp, whi, acc2[j][1]);
            }
        }
    }

    float sc[4], mn[4], bt[4];
#pragma unroll
    for (int dd = 0; dd < 4; dd++) {
        const int d = dq * 4 + dd;
        sc[dd] = __ldg(&gamma[d]) * rsqrtf(__ldg(&var[d]) + 1e-3f);
        mn[dd] = __ldg(&mean[d]);
        bt[dd] = __ldg(&beta[d]);
    }
#pragma unroll
    for (int j = 0; j < 8; j++) {
        float v[4];
        f2unpack(acc2[j][0], v[0], v[1]);
        f2unpack(acc2[j][1], v[2], v[3]);
        const int hw = hw0 + pq * 8 + j;
#pragma unroll
        for (int dd = 0; dd < 4; dd++) {
            const int d = dq * 4 + dd;
            float o = (v[dd] - mn[dd]) * sc[dd] + bt[dd];
            g_r[((size_t)(b * CR + d)) * PIX_PER_B + hw] = fmaxf(o, 0.f);
        }
    }
}

// ---------------------------------------------------------------------------
// K2: grid (14,16,4), 224 threads, 3 CTAs/SM.
// smem layout (floats, 18144 total = 72576B):
//   sm_kg @ 0      : [224][49]  (43904B)   -- live whole kernel after GEMM
//   sm_r  @ 10976  : [16][224]  (14336B)   -- 4 d-chunks during GEMM
//   sm_w  @ 14560  : [64][56]   (14336B)   -- GEMM only
// phase D: X2 (ull) aliases floats [10976 .. ): [c2*437 + rr*62 + col],
//   7 rows x 62 cols x 8 ch-pairs (3493 ull = 27944B), reloaded per row-pass.
// ---------------------------------------------------------------------------
#define KG_F 0
#define R_F  10976
#define W_F  14560
#define SM2_FLOATS 18144

__global__ void __launch_bounds__(224, 3)
k_inv(const float* __restrict__ x,
      const float* __restrict__ w_span,
      const float* __restrict__ b_span,
      float* __restrict__ out)
{
    extern __shared__ float sm2[];
    float* sm_kg = sm2 + KG_F;       // [p][49]
    float* sm_r  = sm2 + R_F;        // [16][224]
    float* sm_w  = sm2 + W_F;        // [d][kh*8 + kw] (pad 7->8)

    const int t  = threadIdx.x;
    const int ht = blockIdx.x;       // 0..13 (4 output rows each)
    const int g  = blockIdx.y;
    const int b  = blockIdx.z;
    const int hw0 = ht * 4 * WW;

    // ---- stage w_span slice: sm_w[d][(k/7)*8 + k%7]
    for (int i = t; i < 64 * 49; i += 224) {
        const int d = i / 49, k = i % 49;
        sm_w[d * 56 + (k / 7) * 8 + (k % 7)] = w_span[(size_t)d * 784 + g * 49 + k];
    }

    const int tp = t & 31;
    const int tk = t >> 5;           // 0..6

    ull  acc2[7][3];
    float accs[7];
#pragma unroll
    for (int j = 0; j < 7; j++) {
        acc2[j][0] = acc2[j][1] = acc2[j][2] = 0ull; accs[j] = 0.f;
    }

    // ---- GEMM over 4 d-chunks of 16
    for (int d0 = 0; d0 < 64; d0 += 16) {
        __syncthreads();             // prev readers done (1st: orders w staging too)
#pragma unroll
        for (int it = 0; it < 4; it++) {
            const int i4 = t + it * 224;
            const int d = i4 / 56, p4 = i4 % 56;
            *(float4*)(sm_r + d * 224 + p4 * 4) =
                *(const float4*)(g_r + ((size_t)(b * CR + d0 + d)) * PIX_PER_B + hw0 + p4 * 4);
        }
        __syncthreads();

#pragma unroll 2
        for (int d = 0; d < 16; d++) {
            const float* rrow = sm_r + d * 224 + tp;
            const float* wrow = sm_w + (d0 + d) * 56 + tk * 8;
            const ull wp0 = *(const ull*)(wrow);
            const ull wp1 = *(const ull*)(wrow + 2);
            const ull wp2 = *(const ull*)(wrow + 4);
            const float w6 = wrow[6];
#pragma unroll
            for (int j = 0; j < 7; j++) {
                const float rv = rrow[32 * j];
                const ull rp = f2splat(rv);
                acc2[j][0] = f2fma(rp, wp0, acc2[j][0]);
                acc2[j][1] = f2fma(rp, wp1, acc2[j][1]);
                acc2[j][2] = f2fma(rp, wp2, acc2[j][2]);
                accs[j] += rv * w6;
            }
        }
    }

    // ---- kgen (+bias) -> smem [p][49]
    float bv[7];
#pragma unroll
    for (int i = 0; i < 7; i++) bv[i] = __ldg(&b_span[g * 49 + tk * 7 + i]);
#pragma unroll
    for (int j = 0; j < 7; j++) {
        const int p = tp + 32 * j;
        float* kgp = sm_kg + p * 49 + tk * 7;
#pragma unroll
        for (int q = 0; q < 3; q++) {
            float lo, hi; f2unpack(acc2[j][q], lo, hi);
            kgp[2 * q]     = lo + bv[2 * q];
            kgp[2 * q + 1] = hi + bv[2 * q + 1];
        }
        kgp[6] = accs[j] + bv[6];
    }

    // ---- involution: 4 single-row passes, 7-row halo each
    ull* X2 = (ull*)(sm2 + R_F);     // [c2*437 + rr*62 + col]
    const int c2   = t & 7;          // channel pair
    const int rgrp = t >> 3;         // 0..27 -> output cols rgrp*2, rgrp*2+1

    for (int pss = 0; pss < 4; pss++) {
        __syncthreads();             // kg written (pass 0) / prev readers done
        // halo rows rr 0..6 <-> global row ht*4+pss-3+rr ; cols 0..61 <-> gcol-3
        for (int idx = t; idx < 8 * 7 * 62; idx += 224) {
            const int cc  = idx & 7;
            const int r2  = idx >> 3;
            const int col = r2 % 62;
            const int rr  = r2 / 62;
            const int grow = ht * 4 + pss - 3 + rr;
            const int gcol = col - 3;
            ull v = 0ull;
            if (grow >= 0 && grow < HH && gcol >= 0 && gcol < WW)
                v = *(const ull*)(x + ((size_t)((b * HH + grow) * WW + gcol)) * CCH + g * 16 + cc * 2);
            X2[cc * 437 + rr * 62 + col] = v;
        }
        __syncthreads();

        const int jc0 = rgrp * 2;
        ull acc0 = 0ull, acc1 = 0ull;
        const float* kg0 = sm_kg + (pss * 56 + jc0) * 49;   // pixel jc0
        const float* kg1 = kg0 + 49;                        // pixel jc0+1
        const ull*   xb  = X2 + c2 * 437 + jc0;

#pragma unroll 1
        for (int kh = 0; kh < 7; kh++) {
            ull xw[8];
            const ull* xr = xb + kh * 62;
#pragma unroll
            for (int u = 0; u < 8; u++) xw[u] = xr[u];
            const float* k0 = kg0 + kh * 7;
            const float* k1 = kg1 + kh * 7;
#pragma unroll
            for (int kw = 0; kw < 7; kw++) {
                acc0 = f2fma(f2splat(k0[kw]), xw[kw],     acc0);
                acc1 = f2fma(f2splat(k1[kw]), xw[kw + 1], acc1);
            }
        }

        const size_t obase =
            ((size_t)((b * HH + ht * 4 + pss) * WW) + jc0) * CCH + g * 16 + c2 * 2;
        float lo, hi;
        f2unpack(acc0, lo, hi);
        *(float2*)(out + obase)       = make_float2(lo, hi);
        f2unpack(acc1, lo, hi);
        *(float2*)(out + obase + CCH) = make_float2(lo, hi);
    }
}

// ---------------------------------------------------------------------------
extern "C" void kernel_launch(void* const* d_in, const int* in_sizes, int n_in,
                              void* d_out, int out_size)
{
    const float* x        = (const float*)d_in[0];
    const float* w_reduce = (const float*)d_in[1];
    const float* gamma    = (const float*)d_in[2];
    const float* beta     = (const float*)d_in[3];
    const float* mean     = (const float*)d_in[4];
    const float* var      = (const float*)d_in[5];
    const float* w_span   = (const float*)d_in[6];
    const float* b_span   = (const float*)d_in[7];
    float* out = (float*)d_out;

    const int smem1 = (64 * 66 + 64 * 68) * 4;   // 34304
    const int smem2 = SM2_FLOATS * 4;            // 72576
    cudaFuncSetAttribute(k_reduce, cudaFuncAttributeMaxDynamicSharedMemorySize, smem1);
    cudaFuncSetAttribute(k_inv,    cudaFuncAttributeMaxDynamicSharedMemorySize, smem2);

    k_reduce<<<NPIX / 64, 128, smem1>>>(x, w_reduce, gamma, beta, mean, var);
    k_inv<<<dim3(14, 16, 4), 224, smem2>>>(x, w_span, b_span, out);
}